// round 7
// baseline (speedup 1.0000x reference)
#include <cuda_runtime.h>
#include <cuda_fp16.h>
#include <math.h>
#include <stdint.h>

#define Bn 1024
#define Tn 64
#define Dn 512
#define Hn 512
#define Cn 96
#define Sn 21
#define DCn (Dn + Cn)   // 608
#define XCn (Dn + Hn)   // 1024
#define NCTA 256

// ---------------- scratch (device globals) ----------------
__device__ __half g_Hp16[(size_t)Bn * Tn * Hn];     // attention score input (fp16)
__device__ __half g_bh16[(size_t)Bn * Tn * Dn];     // ctx accumulation input (fp16)
__device__ float  g_c[Bn * Hn];
__device__ float  g_ph[4 * Bn * Hn];                // 4 split-K partials
__device__ float  g_xcat[Bn * XCn];                 // [ctx | h] fp32
__device__ float  g_hs[(size_t)Bn * Sn * Hn];       // fp32 (output path)
__device__ float  g_Wcat[(size_t)4 * Hn * XCn];     // interleaved rows j=4n+gate
__device__ float  g_ohb[Cn * 4 * Hn];               // Wih one-hot col + biases, interleaved
__device__ unsigned g_bar;                          // grid barrier counter

// ---------------- helpers ----------------
__device__ __forceinline__ float tanh_fast(float x) {
    float y;
    asm("tanh.approx.f32 %0, %1;" : "=f"(y) : "f"(x));
    return y;
}
__device__ __forceinline__ float sigmoidf(float x) {
    return 1.0f / (1.0f + expf(-x));
}

// ---------------- prep ----------------
__global__ void conv_f2h(const float* __restrict__ src, __half* __restrict__ dst, int n8) {
    int i = blockIdx.x * blockDim.x + threadIdx.x;
    if (i >= n8) return;
    float4 a = reinterpret_cast<const float4*>(src)[2 * i];
    float4 b = reinterpret_cast<const float4*>(src)[2 * i + 1];
    __half2* d = reinterpret_cast<__half2*>(dst) + 4 * (size_t)i;
    d[0] = __floats2half2_rn(a.x, a.y);
    d[1] = __floats2half2_rn(a.z, a.w);
    d[2] = __floats2half2_rn(b.x, b.y);
    d[3] = __floats2half2_rn(b.z, b.w);
}
__global__ void build_wcat_kernel(const float* __restrict__ Wih,
                                  const float* __restrict__ Whh) {
    int idx = blockIdx.x * blockDim.x + threadIdx.x;
    if (idx >= 4 * Hn * XCn) return;
    int j = idx >> 10;
    int k = idx & 1023;
    int gate = j & 3, n = j >> 2;
    int r = gate * Hn + n;
    float v = (k < Dn) ? Wih[(size_t)r * DCn + k] : Whh[(size_t)r * Hn + (k - Dn)];
    g_Wcat[idx] = v;
}
__global__ void build_ohb_kernel(const float* __restrict__ Wih,
                                 const float* __restrict__ bih,
                                 const float* __restrict__ bhh) {
    int idx = blockIdx.x * blockDim.x + threadIdx.x;
    if (idx >= Cn * 4 * Hn) return;
    int c = idx / (4 * Hn);
    int j = idx % (4 * Hn);
    int gate = j & 3, n = j >> 2;
    int r = gate * Hn + n;
    g_ohb[idx] = Wih[(size_t)r * DCn + Dn + c] + bih[r] + bhh[r];
}
__global__ void init_state_kernel() {
    int i = blockIdx.x * blockDim.x + threadIdx.x;
    if (i == 0) g_bar = 0u;
    if (i < Bn * Hn) {
        g_c[i] = 0.0f;
        g_xcat[(i / Hn) * XCn + Dn + (i % Hn)] = 0.0f;
    }
}

// ---------------- grid barrier (all NCTA CTAs guaranteed co-resident) ----------------
__device__ __forceinline__ void grid_sync(unsigned target) {
    __syncthreads();
    if (threadIdx.x == 0) {
        __threadfence();
        atomicAdd(&g_bar, 1u);
        volatile unsigned* p = &g_bar;
        while (*p < target) { }
        __threadfence();
    }
    __syncthreads();
}

// ---------------- device GEMM tile (fp16 mma, fp32 in/out) ----------------
// MODE 0: plain fp32 store. MODE 3: fused LSTM epilogue.
// Tile 128x64, K multiple of 32. 256 threads.
template <int MODE>
__device__ __forceinline__ void gemm_tile(
    const float* __restrict__ A, int lda,
    const float* __restrict__ B, int ldb,
    float* __restrict__ C, int ldc,
    int K, int m0, int n0,
    const int* __restrict__ text, int s,
    unsigned char* smraw)
{
    __half* As = reinterpret_cast<__half*>(smraw);                  // [128][40]
    __half* Bs = reinterpret_cast<__half*>(smraw + 128 * 40 * 2);   // [64][40]

    const int tid = threadIdx.x;
    const int warp = tid >> 5, lane = tid & 31;
    const int g = lane >> 2, tig = lane & 3;
    const int wm = warp >> 1, wn = warp & 1;

    const float* Aptr = A + (size_t)m0 * lda;
    const float* Bptr = B + (size_t)n0 * ldb;

    float4 pa[4], pb[2];
    float acc[2][4][4];
#pragma unroll
    for (int i = 0; i < 2; i++)
#pragma unroll
        for (int j = 0; j < 4; j++)
#pragma unroll
            for (int l = 0; l < 4; l++) acc[i][j][l] = 0.0f;

#pragma unroll
    for (int v = 0; v < 4; v++) {
        int f = tid + v * 256;
        pa[v] = *reinterpret_cast<const float4*>(Aptr + (size_t)(f >> 3) * lda + ((f & 7) << 2));
    }
#pragma unroll
    for (int v = 0; v < 2; v++) {
        int f = tid + v * 256;
        pb[v] = *reinterpret_cast<const float4*>(Bptr + (size_t)(f >> 3) * ldb + ((f & 7) << 2));
    }

    for (int k0 = 0; k0 < K; k0 += 32) {
#pragma unroll
        for (int v = 0; v < 4; v++) {
            int f = tid + v * 256; int r = f >> 3, c = (f & 7) << 2;
            *reinterpret_cast<__half2*>(&As[r * 40 + c])     = __floats2half2_rn(pa[v].x, pa[v].y);
            *reinterpret_cast<__half2*>(&As[r * 40 + c + 2]) = __floats2half2_rn(pa[v].z, pa[v].w);
        }
#pragma unroll
        for (int v = 0; v < 2; v++) {
            int f = tid + v * 256; int r = f >> 3, c = (f & 7) << 2;
            *reinterpret_cast<__half2*>(&Bs[r * 40 + c])     = __floats2half2_rn(pb[v].x, pb[v].y);
            *reinterpret_cast<__half2*>(&Bs[r * 40 + c + 2]) = __floats2half2_rn(pb[v].z, pb[v].w);
        }
        __syncthreads();

        if (k0 + 32 < K) {
            const float* An  = Aptr + k0 + 32;
            const float* Bnp = Bptr + k0 + 32;
#pragma unroll
            for (int v = 0; v < 4; v++) {
                int f = tid + v * 256;
                pa[v] = *reinterpret_cast<const float4*>(An + (size_t)(f >> 3) * lda + ((f & 7) << 2));
            }
#pragma unroll
            for (int v = 0; v < 2; v++) {
                int f = tid + v * 256;
                pb[v] = *reinterpret_cast<const float4*>(Bnp + (size_t)(f >> 3) * ldb + ((f & 7) << 2));
            }
        }

#pragma unroll
        for (int ks = 0; ks < 2; ks++) {
            const int kk = ks * 16;
            uint32_t af[2][4], bf[4][2];
#pragma unroll
            for (int mt = 0; mt < 2; mt++) {
                int mb = wm * 32 + mt * 16;
                af[mt][0] = *reinterpret_cast<const uint32_t*>(&As[(mb + g) * 40 + kk + 2 * tig]);
                af[mt][1] = *reinterpret_cast<const uint32_t*>(&As[(mb + g + 8) * 40 + kk + 2 * tig]);
                af[mt][2] = *reinterpret_cast<const uint32_t*>(&As[(mb + g) * 40 + kk + 2 * tig + 8]);
                af[mt][3] = *reinterpret_cast<const uint32_t*>(&As[(mb + g + 8) * 40 + kk + 2 * tig + 8]);
            }
#pragma unroll
            for (int nt = 0; nt < 4; nt++) {
                int nb = wn * 32 + nt * 8 + g;
                bf[nt][0] = *reinterpret_cast<const uint32_t*>(&Bs[nb * 40 + kk + 2 * tig]);
                bf[nt][1] = *reinterpret_cast<const uint32_t*>(&Bs[nb * 40 + kk + 2 * tig + 8]);
            }
#pragma unroll
            for (int mt = 0; mt < 2; mt++)
#pragma unroll
                for (int nt = 0; nt < 4; nt++)
                    asm volatile(
                        "mma.sync.aligned.m16n8k16.row.col.f32.f16.f16.f32 "
                        "{%0,%1,%2,%3}, {%4,%5,%6,%7}, {%8,%9}, {%0,%1,%2,%3};"
                        : "+f"(acc[mt][nt][0]), "+f"(acc[mt][nt][1]),
                          "+f"(acc[mt][nt][2]), "+f"(acc[mt][nt][3])
                        : "r"(af[mt][0]), "r"(af[mt][1]), "r"(af[mt][2]), "r"(af[mt][3]),
                          "r"(bf[nt][0]), "r"(bf[nt][1]));
        }
        __syncthreads();
    }

    if (MODE == 3) {
        float* gbuf = reinterpret_cast<float*>(smraw);   // [128][72]
#pragma unroll
        for (int mt = 0; mt < 2; mt++) {
            int row = wm * 32 + mt * 16 + g;
#pragma unroll
            for (int nt = 0; nt < 4; nt++) {
                int col = wn * 32 + nt * 8 + 2 * tig;
                gbuf[row * 72 + col]           = acc[mt][nt][0];
                gbuf[row * 72 + col + 1]       = acc[mt][nt][1];
                gbuf[(row + 8) * 72 + col]     = acc[mt][nt][2];
                gbuf[(row + 8) * 72 + col + 1] = acc[mt][nt][3];
            }
        }
        __syncthreads();
#pragma unroll
        for (int p = 0; p < 8; p++) {
            int idx = p * 256 + tid;
            int bl = idx >> 4, nl = idx & 15;
            int b = m0 + bl;
            int ng = (n0 >> 2) + nl;
            float4 gv = *reinterpret_cast<const float4*>(&gbuf[bl * 72 + 4 * nl]);
            int tok = text[b * Sn + s];
            float4 ov = *reinterpret_cast<const float4*>(&g_ohb[(size_t)tok * 4 * Hn + 4 * ng]);
            float ig = gv.x + ov.x;
            float fg = gv.y + ov.y;
            float gg = gv.z + ov.z;
            float og = gv.w + ov.w;
            float c_old = g_c[b * Hn + ng];
            float cn = sigmoidf(fg) * c_old + sigmoidf(ig) * tanhf(gg);
            float hn = sigmoidf(og) * tanhf(cn);
            g_c[b * Hn + ng] = cn;
            g_xcat[b * XCn + Dn + ng] = hn;
            g_hs[((size_t)b * Sn + s) * Hn + ng] = hn;
        }
    } else {
#pragma unroll
        for (int mt = 0; mt < 2; mt++) {
            int row = m0 + wm * 32 + mt * 16 + g;
#pragma unroll
            for (int nt = 0; nt < 4; nt++) {
                int col = n0 + wn * 32 + nt * 8 + 2 * tig;
                *reinterpret_cast<float2*>(&C[(size_t)row * ldc + col]) =
                    make_float2(acc[mt][nt][0], acc[mt][nt][1]);
                *reinterpret_cast<float2*>(&C[(size_t)(row + 8) * ldc + col]) =
                    make_float2(acc[mt][nt][2], acc[mt][nt][3]);
            }
        }
    }
}

// ---------------- persistent decoder loop ----------------
__global__ __launch_bounds__(256, 2)
void decoder_kernel(const float* __restrict__ Wh,
                    const float* __restrict__ bhv,
                    const float* __restrict__ Ws,
                    const int* __restrict__ text)
{
    __shared__ __align__(16) unsigned char smraw[36864];
    const int cta = blockIdx.x;
    const int tid = threadIdx.x;
    const int warp = tid >> 5, lane = tid & 31;
    unsigned gen = 0;

    // attn smem carve
    float2* ph2_s   = reinterpret_cast<float2*>(smraw);            // 256
    float2* ws2_s   = ph2_s + 256;                                  // 256
    float*  e_s     = reinterpret_cast<float*>(ws2_s + 256);       // 64
    float*  alpha_s = e_s + 64;                                     // 64

    for (int s = 0; s < Sn; s++) {
        // ---- phase 1: ph split-K GEMM (tile per CTA) ----
        {
            int m0 = (cta & 7) * 128;
            int n0 = ((cta >> 3) & 7) * 64;
            int z  = cta >> 6;                    // 0..3
            gemm_tile<0>(g_xcat + Dn + z * 128, XCn,
                         Wh + z * 128, Hn,
                         g_ph + (size_t)z * Bn * Hn, Hn,
                         128, m0, n0, nullptr, 0, smraw);
        }
        grid_sync(++gen * NCTA);

        // ---- phase 2: attention, 4 batches per CTA ----
        ws2_s[tid] = reinterpret_cast<const float2*>(Ws)[tid];
        {
            float2 bh2v = reinterpret_cast<const float2*>(bhv)[tid];
#pragma unroll 1
            for (int i = 0; i < 4; i++) {
                int b = cta * 4 + i;
                __syncthreads();
                {
                    float2 a = bh2v;
#pragma unroll
                    for (int z = 0; z < 4; z++) {
                        float2 v = reinterpret_cast<const float2*>(
                            g_ph + (size_t)z * Bn * Hn + (size_t)b * Hn)[tid];
                        a.x += v.x; a.y += v.y;
                    }
                    ph2_s[tid] = a;
                }
                __syncthreads();

                const __half2* hp2 = reinterpret_cast<const __half2*>(
                    g_Hp16 + (size_t)b * Tn * Hn);
                for (int t = warp; t < Tn; t += 8) {
                    const __half2* hp = hp2 + t * 256;
                    float a = 0.0f;
#pragma unroll
                    for (int j = 0; j < 8; j++) {
                        int h2 = lane + j * 32;
                        float2 v = __half22float2(hp[h2]);
                        float2 p = ph2_s[h2], w = ws2_s[h2];
                        a = fmaf(tanh_fast(v.x + p.x), w.x, a);
                        a = fmaf(tanh_fast(v.y + p.y), w.y, a);
                    }
#pragma unroll
                    for (int o = 16; o > 0; o >>= 1)
                        a += __shfl_xor_sync(0xffffffffu, a, o);
                    if (lane == 0) e_s[t] = a;
                }
                __syncthreads();

                if (warp == 0) {
                    float e0 = e_s[lane], e1 = e_s[lane + 32];
                    float m = fmaxf(e0, e1);
#pragma unroll
                    for (int o = 16; o > 0; o >>= 1)
                        m = fmaxf(m, __shfl_xor_sync(0xffffffffu, m, o));
                    float x0 = expf(e0 - m), x1 = expf(e1 - m);
                    float sum = x0 + x1;
#pragma unroll
                    for (int o = 16; o > 0; o >>= 1)
                        sum += __shfl_xor_sync(0xffffffffu, sum, o);
                    float inv = 1.0f / sum;
                    alpha_s[lane] = x0 * inv;
                    alpha_s[lane + 32] = x1 * inv;
                }
                __syncthreads();

                const __half2* bh2 = reinterpret_cast<const __half2*>(
                    g_bh16 + (size_t)b * Tn * Dn);
                float ax = 0.0f, ay = 0.0f;
#pragma unroll 8
                for (int t = 0; t < Tn; t++) {
                    float al = alpha_s[t];
                    float2 v = __half22float2(bh2[t * 256 + tid]);
                    ax = fmaf(al, v.x, ax);
                    ay = fmaf(al, v.y, ay);
                }
                reinterpret_cast<float2*>(g_xcat + (size_t)b * XCn)[tid] = make_float2(ax, ay);
            }
        }
        grid_sync(++gen * NCTA);

        // ---- phase 3: gates GEMM + fused LSTM (tile per CTA) ----
        gemm_tile<3>(g_xcat, XCn, g_Wcat, XCn, nullptr, 0,
                     XCn, (cta & 7) * 128, (cta >> 3) * 64, text, s, smraw);
        grid_sync(++gen * NCTA);
    }
}

// ---------------- standalone hgemm (Hp + generator) ----------------
// MODE 2: fp32 C + bias, ragged-N guard.  MODE 4: fp16 C store.
template <int MODE>
__global__ __launch_bounds__(256)
void hgemm(const float* __restrict__ A, int lda,
           const float* __restrict__ B, int ldb,
           const float* __restrict__ bias,
           void* __restrict__ Cv, int ldc,
           int M, int Np, int K)
{
    __shared__ __align__(16) unsigned char smraw[(128 * 40 + 64 * 40) * 2];
    __half* As = reinterpret_cast<__half*>(smraw);
    __half* Bs = reinterpret_cast<__half*>(smraw + 128 * 40 * 2);

    const int tid = threadIdx.x;
    const int warp = tid >> 5, lane = tid & 31;
    const int g = lane >> 2, tig = lane & 3;
    const int wm = warp >> 1, wn = warp & 1;
    const int m0 = blockIdx.y * 128, n0 = blockIdx.x * 64;

    const float* Aptr = A + (size_t)m0 * lda;
    const float* Bptr = B + (size_t)n0 * ldb;

    float4 pa[4], pb[2];
    float acc[2][4][4];
#pragma unroll
    for (int i = 0; i < 2; i++)
#pragma unroll
        for (int j = 0; j < 4; j++)
#pragma unroll
            for (int l = 0; l < 4; l++) acc[i][j][l] = 0.0f;

#pragma unroll
    for (int v = 0; v < 4; v++) {
        int f = tid + v * 256;
        pa[v] = *reinterpret_cast<const float4*>(Aptr + (size_t)(f >> 3) * lda + ((f & 7) << 2));
    }
#pragma unroll
    for (int v = 0; v < 2; v++) {
        int f = tid + v * 256;
        if (MODE == 2 && n0 + (f >> 3) >= Np) pb[v] = make_float4(0.f, 0.f, 0.f, 0.f);
        else pb[v] = *reinterpret_cast<const float4*>(Bptr + (size_t)(f >> 3) * ldb + ((f & 7) << 2));
    }

    for (int k0 = 0; k0 < K; k0 += 32) {
#pragma unroll
        for (int v = 0; v < 4; v++) {
            int f = tid + v * 256; int r = f >> 3, c = (f & 7) << 2;
            *reinterpret_cast<__half2*>(&As[r * 40 + c])     = __floats2half2_rn(pa[v].x, pa[v].y);
            *reinterpret_cast<__half2*>(&As[r * 40 + c + 2]) = __floats2half2_rn(pa[v].z, pa[v].w);
        }
#pragma unroll
        for (int v = 0; v < 2; v++) {
            int f = tid + v * 256; int r = f >> 3, c = (f & 7) << 2;
            *reinterpret_cast<__half2*>(&Bs[r * 40 + c])     = __floats2half2_rn(pb[v].x, pb[v].y);
            *reinterpret_cast<__half2*>(&Bs[r * 40 + c + 2]) = __floats2half2_rn(pb[v].z, pb[v].w);
        }
        __syncthreads();

        if (k0 + 32 < K) {
            const float* An  = Aptr + k0 + 32;
            const float* Bnp = Bptr + k0 + 32;
#pragma unroll
            for (int v = 0; v < 4; v++) {
                int f = tid + v * 256;
                pa[v] = *reinterpret_cast<const float4*>(An + (size_t)(f >> 3) * lda + ((f & 7) << 2));
            }
#pragma unroll
            for (int v = 0; v < 2; v++) {
                int f = tid + v * 256;
                if (MODE == 2 && n0 + (f >> 3) >= Np) pb[v] = make_float4(0.f, 0.f, 0.f, 0.f);
                else pb[v] = *reinterpret_cast<const float4*>(Bnp + (size_t)(f >> 3) * ldb + ((f & 7) << 2));
            }
        }

#pragma unroll
        for (int ks = 0; ks < 2; ks++) {
            const int kk = ks * 16;
            uint32_t af[2][4], bf[4][2];
#pragma unroll
            for (int mt = 0; mt < 2; mt++) {
                int mb = wm * 32 + mt * 16;
                af[mt][0] = *reinterpret_cast<const uint32_t*>(&As[(mb + g) * 40 + kk + 2 * tig]);
                af[mt][1] = *reinterpret_cast<const uint32_t*>(&As[(mb + g + 8) * 40 + kk + 2 * tig]);
                af[mt][2] = *reinterpret_cast<const uint32_t*>(&As[(mb + g) * 40 + kk + 2 * tig + 8]);
                af[mt][3] = *reinterpret_cast<const uint32_t*>(&As[(mb + g + 8) * 40 + kk + 2 * tig + 8]);
            }
#pragma unroll
            for (int nt = 0; nt < 4; nt++) {
                int nb = wn * 32 + nt * 8 + g;
                bf[nt][0] = *reinterpret_cast<const uint32_t*>(&Bs[nb * 40 + kk + 2 * tig]);
                bf[nt][1] = *reinterpret_cast<const uint32_t*>(&Bs[nb * 40 + kk + 2 * tig + 8]);
            }
#pragma unroll
            for (int mt = 0; mt < 2; mt++)
#pragma unroll
                for (int nt = 0; nt < 4; nt++)
                    asm volatile(
                        "mma.sync.aligned.m16n8k16.row.col.f32.f16.f16.f32 "
                        "{%0,%1,%2,%3}, {%4,%5,%6,%7}, {%8,%9}, {%0,%1,%2,%3};"
                        : "+f"(acc[mt][nt][0]), "+f"(acc[mt][nt][1]),
                          "+f"(acc[mt][nt][2]), "+f"(acc[mt][nt][3])
                        : "r"(af[mt][0]), "r"(af[mt][1]), "r"(af[mt][2]), "r"(af[mt][3]),
                          "r"(bf[nt][0]), "r"(bf[nt][1]));
        }
        __syncthreads();
    }

#pragma unroll
    for (int mt = 0; mt < 2; mt++) {
        int row = m0 + wm * 32 + mt * 16 + g;
#pragma unroll
        for (int nt = 0; nt < 4; nt++) {
            int col = n0 + wn * 32 + nt * 8 + 2 * tig;
            if (MODE == 2 && col >= Np) continue;
            if (MODE == 4) {
                __half* C = (__half*)Cv;
                *reinterpret_cast<__half2*>(&C[(size_t)row * ldc + col]) =
                    __floats2half2_rn(acc[mt][nt][0], acc[mt][nt][1]);
                *reinterpret_cast<__half2*>(&C[(size_t)(row + 8) * ldc + col]) =
                    __floats2half2_rn(acc[mt][nt][2], acc[mt][nt][3]);
            } else {
                float* C = (float*)Cv;
                float b0 = bias ? bias[col] : 0.f;
                float b1 = bias ? bias[col + 1] : 0.f;
                *reinterpret_cast<float2*>(&C[(size_t)row * ldc + col]) =
                    make_float2(acc[mt][nt][0] + b0, acc[mt][nt][1] + b1);
                *reinterpret_cast<float2*>(&C[(size_t)(row + 8) * ldc + col]) =
                    make_float2(acc[mt][nt][2] + b0, acc[mt][nt][3] + b1);
            }
        }
    }
}

// ---------------- launch ----------------
extern "C" void kernel_launch(void* const* d_in, const int* in_sizes, int n_in,
                              void* d_out, int out_size)
{
    const float* batch_H = (const float*)d_in[0];
    const int*   text    = (const int*)  d_in[1];
    const float* Wi      = (const float*)d_in[2];
    const float* Wh      = (const float*)d_in[3];
    const float* bh      = (const float*)d_in[4];
    const float* Ws      = (const float*)d_in[5];
    const float* Wih     = (const float*)d_in[6];
    const float* Whh     = (const float*)d_in[7];
    const float* bih     = (const float*)d_in[8];
    const float* bhh     = (const float*)d_in[9];
    const float* Wg      = (const float*)d_in[10];
    const float* bg      = (const float*)d_in[11];
    float* out = (float*)d_out;

    __half *Hp16, *bh16;
    float *hs;
    cudaGetSymbolAddress((void**)&Hp16, g_Hp16);
    cudaGetSymbolAddress((void**)&bh16, g_bh16);
    cudaGetSymbolAddress((void**)&hs,   g_hs);

    // prep
    conv_f2h<<<(Bn * Tn * Dn / 8 + 255) / 256, 256>>>(batch_H, bh16, Bn * Tn * Dn / 8);
    build_wcat_kernel<<<(4 * Hn * XCn + 255) / 256, 256>>>(Wih, Whh);
    build_ohb_kernel<<<(Cn * 4 * Hn + 255) / 256, 256>>>(Wih, bih, bhh);
    init_state_kernel<<<(Bn * Hn + 255) / 256, 256>>>();

    // Hp16 = batch_H @ Wi^T (fp16 mma, fp16 store)
    hgemm<4><<<dim3(Hn / 64, (Bn * Tn) / 128), 256>>>(
        batch_H, Dn, Wi, Dn, nullptr, Hp16, Hn, Bn * Tn, Hn, Dn);

    // persistent 21-step decoder loop
    decoder_kernel<<<NCTA, 256>>>(Wh, bh, Ws, text);

    // probs = hs @ Wg^T + bg  (fp16 mma, fp32 out, ragged N=96)
    hgemm<2><<<dim3(2, (Bn * Sn) / 128), 256>>>(
        hs, Hn, Wg, Hn, bg, out, Cn, Bn * Sn, Cn, Hn);
}

// round 8
// speedup vs baseline: 1.2936x; 1.2936x over previous
#include <cuda_runtime.h>
#include <cuda_fp16.h>
#include <math.h>
#include <stdint.h>

#define Bn 1024
#define Tn 64
#define Dn 512
#define Hn 512
#define Cn 96
#define Sn 21
#define DCn (Dn + Cn)   // 608
#define XCn (Dn + Hn)   // 1024

// ---------------- scratch (device globals) ----------------
__device__ __half g_Hp16[(size_t)Bn * Tn * Hn];     // attention score input (fp16)
__device__ __half g_bh16[(size_t)Bn * Tn * Dn];     // ctx accumulation input (fp16)
__device__ float  g_c[Bn * Hn];
__device__ float  g_ph[2 * Bn * Hn];                // split-K halves
__device__ float  g_xcat[Bn * XCn];                 // [ctx | h] fp32
__device__ float  g_hs[(size_t)Bn * Sn * Hn];       // fp32 (output path)
__device__ __half g_Wcat16[(size_t)4 * Hn * XCn];   // interleaved rows j=4n+gate, fp16
__device__ __half g_Wh16[Hn * Hn];                  // fp16 Wh
__device__ __half g_Wg16[128 * Hn];                 // fp16 Wg padded to 128 rows (zeros)
__device__ float  g_ohb[Cn * 4 * Hn];               // Wih one-hot col + biases, interleaved

// ---------------- helpers ----------------
__device__ __forceinline__ float tanh_fast(float x) {
    float y;
    asm("tanh.approx.f32 %0, %1;" : "=f"(y) : "f"(x));
    return y;
}
__device__ __forceinline__ float sigmoidf(float x) {
    return 1.0f / (1.0f + expf(-x));
}

// ---------------- prep ----------------
__global__ void conv_f2h(const float* __restrict__ src, __half* __restrict__ dst, int n8) {
    int i = blockIdx.x * blockDim.x + threadIdx.x;
    if (i >= n8) return;
    float4 a = reinterpret_cast<const float4*>(src)[2 * i];
    float4 b = reinterpret_cast<const float4*>(src)[2 * i + 1];
    __half2* d = reinterpret_cast<__half2*>(dst) + 4 * (size_t)i;
    d[0] = __floats2half2_rn(a.x, a.y);
    d[1] = __floats2half2_rn(a.z, a.w);
    d[2] = __floats2half2_rn(b.x, b.y);
    d[3] = __floats2half2_rn(b.z, b.w);
}
__global__ void build_wcat_kernel(const float* __restrict__ Wih,
                                  const float* __restrict__ Whh) {
    int idx = blockIdx.x * blockDim.x + threadIdx.x;
    if (idx >= 4 * Hn * XCn) return;
    int j = idx >> 10;
    int k = idx & 1023;
    int gate = j & 3, n = j >> 2;
    int r = gate * Hn + n;
    float v = (k < Dn) ? Wih[(size_t)r * DCn + k] : Whh[(size_t)r * Hn + (k - Dn)];
    g_Wcat16[idx] = __float2half(v);
}
__global__ void build_wg16_kernel(const float* __restrict__ Wg) {
    int idx = blockIdx.x * blockDim.x + threadIdx.x;
    if (idx >= 128 * Hn) return;
    int r = idx >> 9;
    g_Wg16[idx] = __float2half(r < Cn ? Wg[idx] : 0.0f);
}
__global__ void build_ohb_kernel(const float* __restrict__ Wih,
                                 const float* __restrict__ bih,
                                 const float* __restrict__ bhh) {
    int idx = blockIdx.x * blockDim.x + threadIdx.x;
    if (idx >= Cn * 4 * Hn) return;
    int c = idx / (4 * Hn);
    int j = idx % (4 * Hn);
    int gate = j & 3, n = j >> 2;
    int r = gate * Hn + n;
    g_ohb[idx] = Wih[(size_t)r * DCn + Dn + c] + bih[r] + bhh[r];
}
__global__ void init_state_kernel() {
    int i = blockIdx.x * blockDim.x + threadIdx.x;
    if (i < Bn * Hn) {
        g_c[i] = 0.0f;
        g_xcat[(i / Hn) * XCn + Dn + (i % Hn)] = 0.0f;
    }
}

// ---------------- fp16 tensor-core GEMM ----------------
// C[m,n] = sum_k A[m,k]*B[n,k]. A fp32 (converted at smem store); B fp16 if BH.
// Tile 128x64x32, 256 thr, warps 4m x 2n, mma m16n8k16, fp32 accum.
// MODE 1: fp32 C + bias, gridDim.z split-K (bias z==0 only).
// MODE 2: fp32 C + bias, ragged-N store guard (Np).
// MODE 3: fused LSTM epilogue (no C write).
// MODE 4: fp16 C store; blocks with blockIdx.x==0 also mirror A tiles to aux (fp16).
template <int MODE, bool BH>
__global__ __launch_bounds__(256)
void hgemm(const float* __restrict__ A, int lda,
           const void* __restrict__ Bv, int ldb,
           const float* __restrict__ bias,
           void* __restrict__ Cv, int ldc,
           int M, int Np, int K,
           const int* __restrict__ text, int s,
           __half* __restrict__ aux)
{
    __shared__ __align__(16) unsigned char smraw[36864];
    __half* As = reinterpret_cast<__half*>(smraw);                  // [128][40]
    __half* Bs = reinterpret_cast<__half*>(smraw + 128 * 40 * 2);   // [64][40]

    const int tid = threadIdx.x;
    const int warp = tid >> 5, lane = tid & 31;
    const int g = lane >> 2, tig = lane & 3;
    const int wm = warp >> 1, wn = warp & 1;
    const int m0 = blockIdx.y * 128, n0 = blockIdx.x * 64;

    const float* Bf = (const float*)Bv;
    const __half* Bh = (const __half*)Bv;

    if (MODE == 1) {
        int z = blockIdx.z;
        A += (size_t)z * K;
        if (BH) Bh += (size_t)z * K; else Bf += (size_t)z * K;
        Cv = (void*)((float*)Cv + (size_t)z * M * ldc);
        if (z != 0) bias = nullptr;
    }

    const float* Aptr = A + (size_t)m0 * lda;

    float4 pa[4];
    float4 pbf[2];
    uint4 pbh;
    float acc[2][4][4];
#pragma unroll
    for (int i = 0; i < 2; i++)
#pragma unroll
        for (int j = 0; j < 4; j++)
#pragma unroll
            for (int l = 0; l < 4; l++) acc[i][j][l] = 0.0f;

    // prefetch tile 0
#pragma unroll
    for (int v = 0; v < 4; v++) {
        int f = tid + v * 256;
        pa[v] = *reinterpret_cast<const float4*>(Aptr + (size_t)(f >> 3) * lda + ((f & 7) << 2));
    }
    if (BH) {
        int r = tid >> 2, c = (tid & 3) << 3;
        pbh = *reinterpret_cast<const uint4*>(Bh + (size_t)(n0 + r) * ldb + c);
    } else {
#pragma unroll
        for (int v = 0; v < 2; v++) {
            int f = tid + v * 256;
            pbf[v] = *reinterpret_cast<const float4*>(Bf + (size_t)(n0 + (f >> 3)) * ldb + ((f & 7) << 2));
        }
    }

    for (int k0 = 0; k0 < K; k0 += 32) {
        // store A (fp32->fp16) and B to smem
#pragma unroll
        for (int v = 0; v < 4; v++) {
            int f = tid + v * 256; int r = f >> 3, c = (f & 7) << 2;
            __half2 h0 = __floats2half2_rn(pa[v].x, pa[v].y);
            __half2 h1 = __floats2half2_rn(pa[v].z, pa[v].w);
            *reinterpret_cast<__half2*>(&As[r * 40 + c])     = h0;
            *reinterpret_cast<__half2*>(&As[r * 40 + c + 2]) = h1;
            if (MODE == 4) {
                if (blockIdx.x == 0) {
                    __half2* ax = reinterpret_cast<__half2*>(&aux[(size_t)(m0 + r) * lda + k0 + c]);
                    ax[0] = h0; ax[1] = h1;
                }
            }
        }
        if (BH) {
            int r = tid >> 2, c = (tid & 3) << 3;
            *reinterpret_cast<uint4*>(&Bs[r * 40 + c]) = pbh;
        } else {
#pragma unroll
            for (int v = 0; v < 2; v++) {
                int f = tid + v * 256; int r = f >> 3, c = (f & 7) << 2;
                *reinterpret_cast<__half2*>(&Bs[r * 40 + c])     = __floats2half2_rn(pbf[v].x, pbf[v].y);
                *reinterpret_cast<__half2*>(&Bs[r * 40 + c + 2]) = __floats2half2_rn(pbf[v].z, pbf[v].w);
            }
        }
        __syncthreads();

        // prefetch next
        if (k0 + 32 < K) {
            const float* An = Aptr + k0 + 32;
#pragma unroll
            for (int v = 0; v < 4; v++) {
                int f = tid + v * 256;
                pa[v] = *reinterpret_cast<const float4*>(An + (size_t)(f >> 3) * lda + ((f & 7) << 2));
            }
            if (BH) {
                int r = tid >> 2, c = (tid & 3) << 3;
                pbh = *reinterpret_cast<const uint4*>(Bh + (size_t)(n0 + r) * ldb + k0 + 32 + c);
            } else {
#pragma unroll
                for (int v = 0; v < 2; v++) {
                    int f = tid + v * 256;
                    pbf[v] = *reinterpret_cast<const float4*>(Bf + (size_t)(n0 + (f >> 3)) * ldb + k0 + 32 + ((f & 7) << 2));
                }
            }
        }

        // compute: 2 k-steps of 16
#pragma unroll
        for (int ks = 0; ks < 2; ks++) {
            const int kk = ks * 16;
            uint32_t af[2][4], bf[4][2];
#pragma unroll
            for (int mt = 0; mt < 2; mt++) {
                int mb = wm * 32 + mt * 16;
                af[mt][0] = *reinterpret_cast<const uint32_t*>(&As[(mb + g) * 40 + kk + 2 * tig]);
                af[mt][1] = *reinterpret_cast<const uint32_t*>(&As[(mb + g + 8) * 40 + kk + 2 * tig]);
                af[mt][2] = *reinterpret_cast<const uint32_t*>(&As[(mb + g) * 40 + kk + 2 * tig + 8]);
                af[mt][3] = *reinterpret_cast<const uint32_t*>(&As[(mb + g + 8) * 40 + kk + 2 * tig + 8]);
            }
#pragma unroll
            for (int nt = 0; nt < 4; nt++) {
                int nb = wn * 32 + nt * 8 + g;
                bf[nt][0] = *reinterpret_cast<const uint32_t*>(&Bs[nb * 40 + kk + 2 * tig]);
                bf[nt][1] = *reinterpret_cast<const uint32_t*>(&Bs[nb * 40 + kk + 2 * tig + 8]);
            }
#pragma unroll
            for (int mt = 0; mt < 2; mt++)
#pragma unroll
                for (int nt = 0; nt < 4; nt++)
                    asm volatile(
                        "mma.sync.aligned.m16n8k16.row.col.f32.f16.f16.f32 "
                        "{%0,%1,%2,%3}, {%4,%5,%6,%7}, {%8,%9}, {%0,%1,%2,%3};"
                        : "+f"(acc[mt][nt][0]), "+f"(acc[mt][nt][1]),
                          "+f"(acc[mt][nt][2]), "+f"(acc[mt][nt][3])
                        : "r"(af[mt][0]), "r"(af[mt][1]), "r"(af[mt][2]), "r"(af[mt][3]),
                          "r"(bf[nt][0]), "r"(bf[nt][1]));
        }
        __syncthreads();
    }

    if (MODE == 3) {
        // fused LSTM epilogue
        float* gbuf = reinterpret_cast<float*>(smraw);   // [128][72]
#pragma unroll
        for (int mt = 0; mt < 2; mt++) {
            int row = wm * 32 + mt * 16 + g;
#pragma unroll
            for (int nt = 0; nt < 4; nt++) {
                int col = wn * 32 + nt * 8 + 2 * tig;
                gbuf[row * 72 + col]           = acc[mt][nt][0];
                gbuf[row * 72 + col + 1]       = acc[mt][nt][1];
                gbuf[(row + 8) * 72 + col]     = acc[mt][nt][2];
                gbuf[(row + 8) * 72 + col + 1] = acc[mt][nt][3];
            }
        }
        __syncthreads();
#pragma unroll
        for (int p = 0; p < 8; p++) {
            int idx = p * 256 + tid;
            int bl = idx >> 4, nl = idx & 15;
            int b = m0 + bl;
            int ng = (n0 >> 2) + nl;
            float4 gv = *reinterpret_cast<const float4*>(&gbuf[bl * 72 + 4 * nl]);
            int tok = text[b * Sn + s];
            float4 ov = *reinterpret_cast<const float4*>(&g_ohb[(size_t)tok * 4 * Hn + 4 * ng]);
            float ig = gv.x + ov.x;
            float fg = gv.y + ov.y;
            float gg = gv.z + ov.z;
            float og = gv.w + ov.w;
            float c_old = g_c[b * Hn + ng];
            float cn = sigmoidf(fg) * c_old + sigmoidf(ig) * tanhf(gg);
            float hn = sigmoidf(og) * tanhf(cn);
            g_c[b * Hn + ng] = cn;
            g_xcat[b * XCn + Dn + ng] = hn;
            g_hs[((size_t)b * Sn + s) * Hn + ng] = hn;
        }
        return;
    }

#pragma unroll
    for (int mt = 0; mt < 2; mt++) {
        int row = m0 + wm * 32 + mt * 16 + g;
#pragma unroll
        for (int nt = 0; nt < 4; nt++) {
            int col = n0 + wn * 32 + nt * 8 + 2 * tig;
            if (MODE == 2 && col >= Np) continue;
            if (MODE == 4) {
                __half* C = (__half*)Cv;
                *reinterpret_cast<__half2*>(&C[(size_t)row * ldc + col]) =
                    __floats2half2_rn(acc[mt][nt][0], acc[mt][nt][1]);
                *reinterpret_cast<__half2*>(&C[(size_t)(row + 8) * ldc + col]) =
                    __floats2half2_rn(acc[mt][nt][2], acc[mt][nt][3]);
            } else {
                float* C = (float*)Cv;
                float b0 = bias ? bias[col] : 0.f;
                float b1 = bias ? bias[col + 1] : 0.f;
                *reinterpret_cast<float2*>(&C[(size_t)row * ldc + col]) =
                    make_float2(acc[mt][nt][0] + b0, acc[mt][nt][1] + b1);
                *reinterpret_cast<float2*>(&C[(size_t)(row + 8) * ldc + col]) =
                    make_float2(acc[mt][nt][2] + b0, acc[mt][nt][3] + b1);
            }
        }
    }
}

// ---------------- fused attention ----------------
__global__ __launch_bounds__(256)
void attn_kernel(const float* __restrict__ Ws)
{
    const int b = blockIdx.x;
    __shared__ float2 ph2_s[256];
    __shared__ float2 ws2_s[256];
    __shared__ float e_s[Tn];
    __shared__ float alpha_s[Tn];

    const int tid = threadIdx.x;
    {
        const float2* p0 = reinterpret_cast<const float2*>(g_ph + b * Hn);
        const float2* p1 = reinterpret_cast<const float2*>(g_ph + Bn * Hn + b * Hn);
        float2 a = p0[tid], c = p1[tid];
        ph2_s[tid] = make_float2(a.x + c.x, a.y + c.y);
        ws2_s[tid] = reinterpret_cast<const float2*>(Ws)[tid];
    }
    __syncthreads();

    const int warp = tid >> 5, lane = tid & 31;
    const __half2* hp2 = reinterpret_cast<const __half2*>(g_Hp16 + (size_t)b * Tn * Hn);

    // two rows per warp per round (16 outstanding loads/lane)
#pragma unroll
    for (int rr = 0; rr < 4; rr++) {
        int t0 = rr * 16 + warp * 2;
        const __half2* hA = hp2 + (size_t)t0 * 256;
        const __half2* hB = hA + 256;
        float a0 = 0.0f, a1 = 0.0f;
#pragma unroll
        for (int j = 0; j < 8; j++) {
            int h2 = lane + j * 32;
            float2 p = ph2_s[h2], w = ws2_s[h2];
            float2 vA = __half22float2(hA[h2]);
            float2 vB = __half22float2(hB[h2]);
            a0 = fmaf(tanh_fast(vA.x + p.x), w.x, a0);
            a0 = fmaf(tanh_fast(vA.y + p.y), w.y, a0);
            a1 = fmaf(tanh_fast(vB.x + p.x), w.x, a1);
            a1 = fmaf(tanh_fast(vB.y + p.y), w.y, a1);
        }
#pragma unroll
        for (int o = 16; o > 0; o >>= 1) {
            a0 += __shfl_xor_sync(0xffffffffu, a0, o);
            a1 += __shfl_xor_sync(0xffffffffu, a1, o);
        }
        if (lane == 0) { e_s[t0] = a0; e_s[t0 + 1] = a1; }
    }
    __syncthreads();

    if (warp == 0) {
        float e0 = e_s[lane], e1 = e_s[lane + 32];
        float m = fmaxf(e0, e1);
#pragma unroll
        for (int o = 16; o > 0; o >>= 1)
            m = fmaxf(m, __shfl_xor_sync(0xffffffffu, m, o));
        float x0 = expf(e0 - m), x1 = expf(e1 - m);
        float sum = x0 + x1;
#pragma unroll
        for (int o = 16; o > 0; o >>= 1)
            sum += __shfl_xor_sync(0xffffffffu, sum, o);
        float inv = 1.0f / sum;
        alpha_s[lane] = x0 * inv;
        alpha_s[lane + 32] = x1 * inv;
    }
    __syncthreads();

    const __half2* bh2 = reinterpret_cast<const __half2*>(g_bh16 + (size_t)b * Tn * Dn);
    float ax = 0.0f, ay = 0.0f;
#pragma unroll 16
    for (int t = 0; t < Tn; t++) {
        float al = alpha_s[t];
        float2 v = __half22float2(bh2[t * 256 + tid]);
        ax = fmaf(al, v.x, ax);
        ay = fmaf(al, v.y, ay);
    }
    reinterpret_cast<float2*>(g_xcat + (size_t)b * XCn)[tid] = make_float2(ax, ay);
}

// ---------------- launch ----------------
extern "C" void kernel_launch(void* const* d_in, const int* in_sizes, int n_in,
                              void* d_out, int out_size)
{
    const float* batch_H = (const float*)d_in[0];
    const int*   text    = (const int*)  d_in[1];
    const float* Wi      = (const float*)d_in[2];
    const float* Wh      = (const float*)d_in[3];
    const float* bh      = (const float*)d_in[4];
    const float* Ws      = (const float*)d_in[5];
    const float* Wih     = (const float*)d_in[6];
    const float* Whh     = (const float*)d_in[7];
    const float* bih     = (const float*)d_in[8];
    const float* bhh     = (const float*)d_in[9];
    const float* Wg      = (const float*)d_in[10];
    const float* bg      = (const float*)d_in[11];
    float* out = (float*)d_out;

    __half *Hp16, *bh16, *Wcat16, *Wh16, *Wg16;
    float *ph, *xcat, *hs;
    cudaGetSymbolAddress((void**)&Hp16,   g_Hp16);
    cudaGetSymbolAddress((void**)&bh16,   g_bh16);
    cudaGetSymbolAddress((void**)&Wcat16, g_Wcat16);
    cudaGetSymbolAddress((void**)&Wh16,   g_Wh16);
    cudaGetSymbolAddress((void**)&Wg16,   g_Wg16);
    cudaGetSymbolAddress((void**)&ph,     g_ph);
    cudaGetSymbolAddress((void**)&xcat,   g_xcat);
    cudaGetSymbolAddress((void**)&hs,     g_hs);

    // prep
    build_wcat_kernel<<<(4 * Hn * XCn + 255) / 256, 256>>>(Wih, Whh);
    conv_f2h<<<(Hn * Hn / 8 + 255) / 256, 256>>>(Wh, Wh16, Hn * Hn / 8);
    build_wg16_kernel<<<(128 * Hn + 255) / 256, 256>>>(Wg);
    build_ohb_kernel<<<(Cn * 4 * Hn + 255) / 256, 256>>>(Wih, bih, bhh);
    init_state_kernel<<<(Bn * Hn + 255) / 256, 256>>>();

    // Hp16 = batch_H @ Wi^T (fp16 mma, fp16 store); n0==0 blocks mirror batch_H -> bh16
    hgemm<4, false><<<dim3(Hn / 64, (Bn * Tn) / 128), 256>>>(
        batch_H, Dn, Wi, Dn, nullptr, Hp16, Hn, Bn * Tn, Hn, Dn, nullptr, 0, bh16);

    for (int s = 0; s < Sn; s++) {
        // ph halves: z in {0,1}, K=256 each (bias on z=0)
        hgemm<1, true><<<dim3(Hn / 64, Bn / 128, 2), 256>>>(
            xcat + Dn, XCn, Wh16, Hn, bh, ph, Hn, Bn, Hn, 256, nullptr, 0, nullptr);

        attn_kernel<<<Bn, 256>>>(Ws);

        // gates (interleaved Wcat16) + fused LSTM
        hgemm<3, true><<<dim3(4 * Hn / 64, Bn / 128), 256>>>(
            xcat, XCn, Wcat16, XCn, nullptr, nullptr, 0, Bn, 4 * Hn, XCn, text, s, nullptr);
    }

    // probs = hs @ Wg^T + bg  (fp16 mma, fp32 out, N padded to 128, store guard 96)
    hgemm<2, true><<<dim3(2, (Bn * Sn) / 128), 256>>>(
        hs, Hn, Wg16, Hn, bg, out, Cn, Bn * Sn, Cn, Hn, nullptr, 0, nullptr);
}